// round 2
// baseline (speedup 1.0000x reference)
#include <cuda_runtime.h>
#include <math.h>

#define RDIM 8192
#define CDIM 2048
#define HID 20
#define NBLK 32

// ---------------- device scratch ----------------
__device__ float g_G   [(size_t)RDIM * CDIM];
__device__ float g_P0  [(size_t)RDIM * CDIM];
__device__ float g_B   [(size_t)RDIM * CDIM];
__device__ float g_A   [(size_t)CDIM * CDIM];
__device__ float g_As  [(size_t)CDIM * CDIM];
__device__ float g_Gram[(size_t)CDIM * CDIM];   // becomes R (upper) after Cholesky
__device__ float g_Rinv[(size_t)CDIM * CDIM];
__device__ float g_rowp[16 * (size_t)RDIM];
__device__ float g_dL[RDIM];
__device__ float g_dR[CDIM];
__device__ float g_lraw[RDIM];
__device__ float g_rraw[CDIM];
__device__ float g_partL[32];
__device__ float g_partR[8];
__device__ float g_means[2];
__device__ float g_Lv[RDIM];
__device__ float g_Rv[CDIM];

// All matrices column-major. C(MxN)=alpha*A^T*B(+Cin). A: K x M (lda), B: K x N (ldb). K%16==0.
__global__ __launch_bounds__(256) void gemm_tn(
    const float* __restrict__ A, int lda, const float* __restrict__ B, int ldb,
    const float* __restrict__ Cin, float* __restrict__ Cout, int ldc,
    int K, float alpha, int upperOnly)
{
    int p0 = blockIdx.x * 64, q0 = blockIdx.y * 64;
    if (upperOnly && q0 < p0) return;
    __shared__ float As[16][68];
    __shared__ float Bs[16][68];
    int tid = threadIdx.x, tx = tid & 15, ty = tid >> 4;
    float acc[4][4];
#pragma unroll
    for (int a = 0; a < 4; a++)
#pragma unroll
        for (int b = 0; b < 4; b++) acc[a][b] = 0.f;
    for (int k0 = 0; k0 < K; k0 += 16) {
#pragma unroll
        for (int s2 = 0; s2 < 4; s2++) {
            int idx = tid + s2 * 256;
            int kk = idx & 15, pp = idx >> 4;
            As[kk][pp] = A[(size_t)(p0 + pp) * lda + (k0 + kk)];
            Bs[kk][pp] = B[(size_t)(q0 + pp) * ldb + (k0 + kk)];
        }
        __syncthreads();
#pragma unroll
        for (int kk = 0; kk < 16; kk++) {
            float4 av = *(const float4*)&As[kk][ty * 4];
            float4 bv = *(const float4*)&Bs[kk][tx * 4];
            float ar[4] = {av.x, av.y, av.z, av.w};
            float br[4] = {bv.x, bv.y, bv.z, bv.w};
#pragma unroll
            for (int a = 0; a < 4; a++)
#pragma unroll
                for (int b = 0; b < 4; b++)
                    acc[a][b] = fmaf(ar[a], br[b], acc[a][b]);
        }
        __syncthreads();
    }
#pragma unroll
    for (int a = 0; a < 4; a++)
#pragma unroll
        for (int b = 0; b < 4; b++) {
            int p = p0 + ty * 4 + a, q = q0 + tx * 4 + b;
            size_t o = (size_t)q * ldc + p;
            float v = alpha * acc[a][b];
            if (Cin) v += Cin[o];
            Cout[o] = v;
        }
}

// C = gamma*(A*S) + alpha*X + beta*Y. A: M x K (lda), S: K x N (lds). triK: only k<q0+64.
__global__ __launch_bounds__(256) void gemm_nn(
    const float* __restrict__ A, int lda, const float* __restrict__ S, int lds,
    const float* __restrict__ X, float alpha, const float* __restrict__ Y, float beta,
    float gamma, float* __restrict__ Cout, int ldc, int K, int triK)
{
    int i0 = blockIdx.x * 64, q0 = blockIdx.y * 64;
    int kmax = triK ? (q0 + 64) : K;
    if (kmax > K) kmax = K;
    __shared__ float As[16][68];
    __shared__ float Ss[16][68];
    int tid = threadIdx.x, tx = tid & 15, ty = tid >> 4;
    float acc[4][4];
#pragma unroll
    for (int a = 0; a < 4; a++)
#pragma unroll
        for (int b = 0; b < 4; b++) acc[a][b] = 0.f;
    for (int k0 = 0; k0 < kmax; k0 += 16) {
#pragma unroll
        for (int s2 = 0; s2 < 4; s2++) {
            int idx = tid + s2 * 256;
            int ii = idx & 63, kk = idx >> 6;
            As[kk][ii] = A[(size_t)(k0 + kk) * lda + (i0 + ii)];
            int kk2 = idx & 15, qq = idx >> 4;
            Ss[kk2][qq] = S[(size_t)(q0 + qq) * lds + (k0 + kk2)];
        }
        __syncthreads();
#pragma unroll
        for (int kk = 0; kk < 16; kk++) {
            float4 av = *(const float4*)&As[kk][ty * 4];
            float4 bv = *(const float4*)&Ss[kk][tx * 4];
            float ar[4] = {av.x, av.y, av.z, av.w};
            float br[4] = {bv.x, bv.y, bv.z, bv.w};
#pragma unroll
            for (int a = 0; a < 4; a++)
#pragma unroll
                for (int b = 0; b < 4; b++)
                    acc[a][b] = fmaf(ar[a], br[b], acc[a][b]);
        }
        __syncthreads();
    }
#pragma unroll
    for (int a = 0; a < 4; a++)
#pragma unroll
        for (int b = 0; b < 4; b++) {
            int p = i0 + ty * 4 + a, q = q0 + tx * 4 + b;
            size_t o = (size_t)q * ldc + p;
            float v = gamma * acc[a][b];
            if (X) v += alpha * X[o];
            if (Y) v += beta * Y[o];
            Cout[o] = v;
        }
}

__global__ void symK(const float* __restrict__ in, float* __restrict__ outp) {
    int idx = blockIdx.x * 256 + threadIdx.x;
    int p = idx & (CDIM - 1), q = idx >> 11;
    outp[idx] = 0.5f * (in[idx] + in[(size_t)p * CDIM + q]);
}

__global__ void rowsqK() {  // grid (RDIM/256, 16)
    int i = blockIdx.x * 256 + threadIdx.x;
    int q0 = blockIdx.y * (CDIM / 16);
    float acc = 0.f;
    for (int q = q0; q < q0 + CDIM / 16; q++) {
        float v = g_G[(size_t)q * RDIM + i];
        acc += v * v;
    }
    g_rowp[(size_t)blockIdx.y * RDIM + i] = acc;
}
__global__ void rowcombK() {
    int i = blockIdx.x * 256 + threadIdx.x;
    float s = 0.f;
    for (int ch = 0; ch < 16; ch++) s += g_rowp[(size_t)ch * RDIM + i];
    g_dL[i] = s / (float)CDIM;
}
__global__ void colsqK() {
    __shared__ float red[256];
    int q = blockIdx.x, tid = threadIdx.x;
    const float* col = g_G + (size_t)q * RDIM;
    float acc = 0.f;
    for (int i = tid; i < RDIM; i += 256) { float v = col[i]; acc += v * v; }
    red[tid] = acc; __syncthreads();
    for (int s = 128; s > 0; s >>= 1) { if (tid < s) red[tid] += red[tid + s]; __syncthreads(); }
    if (tid == 0) g_dR[q] = red[0] / (float)RDIM;
}

__device__ __forceinline__ float sigm(float x) { return 1.f / (1.f + expf(-x)); }

__global__ __launch_bounds__(256) void lstmK(
    int N, const float* __restrict__ diag,
    const float* __restrict__ h0, const float* __restrict__ c0,
    const float* __restrict__ Wih0, const float* __restrict__ Whh0,
    const float* __restrict__ bih0, const float* __restrict__ bhh0,
    const float* __restrict__ Wih1, const float* __restrict__ Whh1,
    const float* __restrict__ bih1, const float* __restrict__ bhh1,
    const float* __restrict__ LW, const float* __restrict__ Lb,
    float* __restrict__ raw, float* __restrict__ part)
{
    __shared__ float sWih0[80], sB0[80], sB1[80];
    __shared__ float sWhh0[1600], sWih1[1600], sWhh1[1600];
    __shared__ float sLW[HID];
    int tid = threadIdx.x;
    for (int k = tid; k < 80; k += 256) {
        sWih0[k] = Wih0[k];
        sB0[k] = bih0[k] + bhh0[k];
        sB1[k] = bih1[k] + bhh1[k];
    }
    for (int k = tid; k < 1600; k += 256) {
        sWhh0[k] = Whh0[k]; sWih1[k] = Wih1[k]; sWhh1[k] = Whh1[k];
    }
    if (tid < HID) sLW[tid] = LW[tid];
    __syncthreads();

    int n = blockIdx.x * 256 + tid;
    float d = diag[n];
    float x = logf(fabsf(d)) * 0.1f;
    x = fminf(fmaxf(x, -1.f), 1.f);

    float hp[HID], h1[HID];
    const float* h0p = h0 + (size_t)n * HID;
    const float* c0p = c0 + (size_t)n * HID;
#pragma unroll
    for (int j = 0; j < HID; j++) hp[j] = h0p[j];
    for (int jh = 0; jh < HID; jh++) {
        float gi = sB0[jh]      + sWih0[jh] * x;
        float gf = sB0[20 + jh] + sWih0[20 + jh] * x;
        float gg = sB0[40 + jh] + sWih0[40 + jh] * x;
        float go = sB0[60 + jh] + sWih0[60 + jh] * x;
#pragma unroll
        for (int j = 0; j < HID; j++) {
            float hv = hp[j];
            gi = fmaf(sWhh0[jh * 20 + j], hv, gi);
            gf = fmaf(sWhh0[(20 + jh) * 20 + j], hv, gf);
            gg = fmaf(sWhh0[(40 + jh) * 20 + j], hv, gg);
            go = fmaf(sWhh0[(60 + jh) * 20 + j], hv, go);
        }
        float cc = sigm(gf) * c0p[jh] + sigm(gi) * tanhf(gg);
        h1[jh] = sigm(go) * tanhf(cc);
    }
    const float* h1p = h0 + (size_t)N * HID + (size_t)n * HID;
    const float* c1p = c0 + (size_t)N * HID + (size_t)n * HID;
    float hb[HID];
#pragma unroll
    for (int j = 0; j < HID; j++) hb[j] = h1p[j];
    float o = 0.f;
    for (int jh = 0; jh < HID; jh++) {
        float gi = sB1[jh], gf = sB1[20 + jh], gg = sB1[40 + jh], go = sB1[60 + jh];
#pragma unroll
        for (int j = 0; j < HID; j++) {
            float a = h1[j], b = hb[j];
            gi = fmaf(sWih1[jh * 20 + j], a, fmaf(sWhh1[jh * 20 + j], b, gi));
            gf = fmaf(sWih1[(20 + jh) * 20 + j], a, fmaf(sWhh1[(20 + jh) * 20 + j], b, gf));
            gg = fmaf(sWih1[(40 + jh) * 20 + j], a, fmaf(sWhh1[(40 + jh) * 20 + j], b, gg));
            go = fmaf(sWih1[(60 + jh) * 20 + j], a, fmaf(sWhh1[(60 + jh) * 20 + j], b, go));
        }
        float cc = sigm(gf) * c1p[jh] + sigm(gi) * tanhf(gg);
        float h2 = sigm(go) * tanhf(cc);
        o = fmaf(sLW[jh], h2, o);
    }
    float val = (o + Lb[0]) * 0.1f;
    raw[n] = val;

    __shared__ float red[256];
    red[tid] = val; __syncthreads();
    for (int s = 128; s > 0; s >>= 1) { if (tid < s) red[tid] += red[tid + s]; __syncthreads(); }
    if (tid == 0) part[blockIdx.x] = red[0];
}

__global__ void meansK() {
    if (threadIdx.x == 0) {
        float s = 0.f; for (int i = 0; i < 32; i++) s += g_partL[i];
        g_means[0] = s / (float)RDIM;
        float t = 0.f; for (int i = 0; i < 8; i++) t += g_partR[i];
        g_means[1] = t / (float)CDIM;
    }
}

__global__ void applyK(const float* __restrict__ raw, const float* __restrict__ before,
                       int mi, float* __restrict__ outv) {
    int i = blockIdx.x * 256 + threadIdx.x;
    outv[i] = fmaxf(raw[i] - g_means[mi] + 1.0f, before[i]);
}

__global__ void p0K() {
    size_t idx = (size_t)blockIdx.x * 256 + threadIdx.x;
    int i = (int)(idx & (RDIM - 1));
    int q = (int)(idx >> 13);
    g_P0[idx] = g_Lv[i] * g_G[idx] * g_Rv[q];
}

// blocked upper Cholesky diag: Gram_kk -> R_kk (in place)
__global__ void cholDiagK(int k0) {
    __shared__ float S[64][65];
    int t = threadIdx.x;
    for (int e = t; e < 4096; e += 64) {
        int a = e & 63, b = e >> 6;
        S[a][b] = g_Gram[(size_t)(k0 + b) * CDIM + (k0 + a)];
    }
    __syncthreads();
    for (int j = 0; j < 64; j++) {
        if (t == 0) S[j][j] = sqrtf(S[j][j]);
        __syncthreads();
        float rjj = S[j][j];
        if (t > j) S[j][t] /= rjj;
        __syncthreads();
        if (t > j) {
            float sjt = S[j][t];
            for (int a = j + 1; a <= t; a++) S[a][t] -= S[j][a] * sjt;
        }
        __syncthreads();
    }
    for (int e = t; e < 4096; e += 64) {
        int a = e & 63, b = e >> 6;
        if (a <= b) g_Gram[(size_t)(k0 + b) * CDIM + (k0 + a)] = S[a][b];
    }
}

// solve R_kk^T X = panel (64 cols per block)
__global__ void cholTrsmK(int k0) {
    __shared__ float Rkk[64][65];
    __shared__ float Xs[64][65];
    int t = threadIdx.x;
    int qb = k0 + 64 + blockIdx.x * 64;
    for (int e = t; e < 4096; e += 64) {
        int a = e & 63, b = e >> 6;
        Rkk[a][b] = g_Gram[(size_t)(k0 + b) * CDIM + (k0 + a)];
        Xs[a][b]  = g_Gram[(size_t)(qb + b) * CDIM + (k0 + a)];
    }
    __syncthreads();
    for (int a = 0; a < 64; a++) {
        float sum = 0.f;
        for (int b = 0; b < a; b++) sum = fmaf(Rkk[b][a], Xs[b][t], sum);
        Xs[a][t] = (Xs[a][t] - sum) / Rkk[a][a];
    }
    __syncthreads();
    for (int e = t; e < 4096; e += 64) {
        int a = e & 63, b = e >> 6;
        g_Gram[(size_t)(qb + b) * CDIM + (k0 + a)] = Xs[a][b];
    }
}

// invert diag blocks of R into Rinv (zeros below diag)
__global__ void invDiagK() {
    int k0 = blockIdx.x * 64;
    __shared__ float U[64][65];
    __shared__ float Xs[64][65];
    int t = threadIdx.x;
    for (int e = t; e < 4096; e += 64) {
        int a = e & 63, b = e >> 6;
        U[a][b] = (a <= b) ? g_Gram[(size_t)(k0 + b) * CDIM + (k0 + a)] : 0.f;
        Xs[a][b] = 0.f;
    }
    __syncthreads();
    for (int a = 63; a >= 0; a--) {
        if (a <= t) {
            float sum = (a == t) ? 1.f : 0.f;
            for (int b = a + 1; b <= t; b++) sum = fmaf(-U[a][b], Xs[b][t], sum);
            Xs[a][t] = sum / U[a][a];
        }
    }
    __syncthreads();
    for (int e = t; e < 4096; e += 64) {
        int a = e & 63, b = e >> 6;
        g_Rinv[(size_t)(k0 + b) * CDIM + (k0 + a)] = Xs[a][b];
    }
}

// off-diagonal blocks of Rinv, by diagonal d: X(i,i+d) = -X_ii * sum_{k=i+1..i+d} R(i,k) X(k,i+d)
__global__ __launch_bounds__(256) void invOffK(int d) {
    int i = blockIdx.x, j = i + d;
    __shared__ float As[16][68];
    __shared__ float Bs[16][68];
    __shared__ float Ws[64][68];
    __shared__ float Us[64][68];
    int tid = threadIdx.x, tx = tid & 15, ty = tid >> 4;
    float acc[4][4];
#pragma unroll
    for (int a = 0; a < 4; a++)
#pragma unroll
        for (int b = 0; b < 4; b++) acc[a][b] = 0.f;
    for (int kb = i + 1; kb <= j; kb++) {
        for (int k16 = 0; k16 < 64; k16 += 16) {
#pragma unroll
            for (int s2 = 0; s2 < 4; s2++) {
                int idx = tid + s2 * 256;
                int pp = idx & 63, kk = idx >> 6;
                As[kk][pp] = g_Gram[(size_t)(kb * 64 + k16 + kk) * CDIM + (i * 64 + pp)];
                int kk2 = idx & 15, qq = idx >> 4;
                Bs[kk2][qq] = g_Rinv[(size_t)(j * 64 + qq) * CDIM + (kb * 64 + k16 + kk2)];
            }
            __syncthreads();
#pragma unroll
            for (int kk = 0; kk < 16; kk++) {
                float4 av = *(const float4*)&As[kk][ty * 4];
                float4 bv = *(const float4*)&Bs[kk][tx * 4];
                float ar[4] = {av.x, av.y, av.z, av.w};
                float br[4] = {bv.x, bv.y, bv.z, bv.w};
#pragma unroll
                for (int a = 0; a < 4; a++)
#pragma unroll
                    for (int b = 0; b < 4; b++)
                        acc[a][b] = fmaf(ar[a], br[b], acc[a][b]);
            }
            __syncthreads();
        }
    }
#pragma unroll
    for (int a = 0; a < 4; a++)
#pragma unroll
        for (int b = 0; b < 4; b++) Ws[ty * 4 + a][tx * 4 + b] = acc[a][b];
    for (int e = tid; e < 4096; e += 256) {
        int aa = e & 63, bb = e >> 6;
        Us[aa][bb] = g_Rinv[(size_t)(i * 64 + bb) * CDIM + (i * 64 + aa)];
    }
    __syncthreads();
#pragma unroll
    for (int a = 0; a < 4; a++) {
        int p = ty * 4 + a;
#pragma unroll
        for (int b = 0; b < 4; b++) {
            int q = tx * 4 + b;
            float s = 0.f;
            for (int m = p; m < 64; m++) s = fmaf(Us[p][m], Ws[m][q], s);
            g_Rinv[(size_t)(j * 64 + q) * CDIM + (i * 64 + p)] = -s;
        }
    }
}

extern "C" void kernel_launch(void* const* d_in, const int* in_sizes, int n_in,
                              void* d_out, int out_size) {
    const float* s   = (const float*)d_in[0];
    const float* sg  = (const float*)d_in[1];
    const float* Lh0 = (const float*)d_in[2];
    const float* Lc0 = (const float*)d_in[3];
    const float* Rh0 = (const float*)d_in[4];
    const float* Rc0 = (const float*)d_in[5];
    const float* Lbef = (const float*)d_in[6];
    const float* Rbef = (const float*)d_in[7];
    const float* Wih0 = (const float*)d_in[8];
    const float* Whh0 = (const float*)d_in[9];
    const float* bih0 = (const float*)d_in[10];
    const float* bhh0 = (const float*)d_in[11];
    const float* Wih1 = (const float*)d_in[12];
    const float* Whh1 = (const float*)d_in[13];
    const float* bih1 = (const float*)d_in[14];
    const float* bhh1 = (const float*)d_in[15];
    const float* LW = (const float*)d_in[16];
    const float* Lb = (const float*)d_in[17];
    const float* RW = (const float*)d_in[18];
    const float* Rb = (const float*)d_in[19];
    float* out = (float*)d_out;

    float *gG, *gP0, *gB, *gA, *gAs, *gGram, *gRinv;
    float *gdL, *gdR, *glraw, *grraw, *gpartL, *gpartR, *gLv, *gRv;
    cudaGetSymbolAddress((void**)&gG, g_G);
    cudaGetSymbolAddress((void**)&gP0, g_P0);
    cudaGetSymbolAddress((void**)&gB, g_B);
    cudaGetSymbolAddress((void**)&gA, g_A);
    cudaGetSymbolAddress((void**)&gAs, g_As);
    cudaGetSymbolAddress((void**)&gGram, g_Gram);
    cudaGetSymbolAddress((void**)&gRinv, g_Rinv);
    cudaGetSymbolAddress((void**)&gdL, g_dL);
    cudaGetSymbolAddress((void**)&gdR, g_dR);
    cudaGetSymbolAddress((void**)&glraw, g_lraw);
    cudaGetSymbolAddress((void**)&grraw, g_rraw);
    cudaGetSymbolAddress((void**)&gpartL, g_partL);
    cudaGetSymbolAddress((void**)&gpartR, g_partR);
    cudaGetSymbolAddress((void**)&gLv, g_Lv);
    cudaGetSymbolAddress((void**)&gRv, g_Rv);

    // A = M^T * (0.1*Mgrad)   (2048x2048)
    gemm_tn<<<dim3(32, 32), 256>>>(s, RDIM, sg, RDIM, nullptr, gA, CDIM, RDIM, 0.1f, 0);
    symK<<<CDIM * CDIM / 256, 256>>>(gA, gAs);
    // G = 0.1*Mgrad - M*As
    gemm_nn<<<dim3(128, 32), 256>>>(s, RDIM, gAs, CDIM, sg, 0.1f, nullptr, 0.f, -1.f, gG, RDIM, CDIM, 0);
    // Gram diagonals
    rowsqK<<<dim3(32, 16), 256>>>();
    rowcombK<<<32, 256>>>();
    colsqK<<<CDIM, 256>>>();
    // LSTMs
    lstmK<<<32, 256>>>(RDIM, gdL, Lh0, Lc0, Wih0, Whh0, bih0, bhh0, Wih1, Whh1, bih1, bhh1, LW, Lb, glraw, gpartL);
    lstmK<<<8, 256>>>(CDIM, gdR, Rh0, Rc0, Wih0, Whh0, bih0, bhh0, Wih1, Whh1, bih1, bhh1, RW, Rb, grraw, gpartR);
    meansK<<<1, 32>>>();
    applyK<<<32, 256>>>(glraw, Lbef, 0, gLv);
    applyK<<<8, 256>>>(grraw, Rbef, 1, gRv);
    // P0 = Lv . G . Rv
    p0K<<<(unsigned)((size_t)RDIM * CDIM / 256), 256>>>();
    // A2 = M^T*P0 ; As2 = sym ; B = M - P0 + M*As2
    gemm_tn<<<dim3(32, 32), 256>>>(s, RDIM, gP0, RDIM, nullptr, gA, CDIM, RDIM, 1.f, 0);
    symK<<<CDIM * CDIM / 256, 256>>>(gA, gAs);
    gemm_nn<<<dim3(128, 32), 256>>>(s, RDIM, gAs, CDIM, s, 1.f, gP0, -1.f, 1.f, gB, RDIM, CDIM, 0);
    // Gram = B^T B (upper)
    gemm_tn<<<dim3(32, 32), 256>>>(gB, RDIM, gB, RDIM, nullptr, gGram, CDIM, RDIM, 1.f, 1);
    // blocked Cholesky
    for (int k = 0; k < NBLK; k++) {
        cholDiagK<<<1, 64>>>(k * 64);
        int nb = NBLK - 1 - k;
        if (nb > 0) {
            cholTrsmK<<<nb, 64>>>(k * 64);
            int r0 = (k + 1) * 64;
            const float* panel = gGram + (size_t)r0 * CDIM + k * 64;
            float* base = gGram + (size_t)r0 * CDIM + r0;
            gemm_tn<<<dim3(nb, nb), 256>>>(panel, CDIM, panel, CDIM, base, base, CDIM, 64, -1.f, 1);
        }
    }
    // Rinv
    invDiagK<<<NBLK, 64>>>();
    for (int d = 1; d < NBLK; d++) invOffK<<<NBLK - d, 256>>>(d);
    // Q = B * Rinv  -> out (new_s)
    gemm_nn<<<dim3(128, 32), 256>>>(gB, RDIM, gRinv, CDIM, nullptr, 0.f, nullptr, 0.f, 1.f, out, RDIM, CDIM, 1);
}

// round 3
// speedup vs baseline: 1.4745x; 1.4745x over previous
#include <cuda_runtime.h>
#include <cuda_bf16.h>
#include <math.h>

#define RDIM 8192
#define CDIM 2048
#define HID 20
#define NBLK 32
#define PIT 26   // SMEM row pitch (bf16 halves) for 16-wide k tiles

// ---------------- device scratch ----------------
__device__ float g_G   [(size_t)RDIM * CDIM];
__device__ float g_P0  [(size_t)RDIM * CDIM];
__device__ float g_B   [(size_t)RDIM * CDIM];
__device__ float g_A   [(size_t)CDIM * CDIM];
__device__ float g_As  [(size_t)CDIM * CDIM];
__device__ float g_Gram[(size_t)CDIM * CDIM];
__device__ float g_Rinv[(size_t)CDIM * CDIM];
__device__ float g_rowp[16 * (size_t)RDIM];
__device__ float g_dL[RDIM];
__device__ float g_dR[CDIM];
__device__ float g_lraw[RDIM];
__device__ float g_rraw[CDIM];
__device__ float g_partL[32];
__device__ float g_partR[8];
__device__ float g_means[2];
__device__ float g_Lv[RDIM];
__device__ float g_Rv[CDIM];

// ---------------- tensor-core helpers ----------------
__device__ __forceinline__ void mma_bf16(float* c, const unsigned* a, const unsigned* b) {
    asm volatile(
        "mma.sync.aligned.m16n8k16.row.col.f32.bf16.bf16.f32 "
        "{%0,%1,%2,%3},{%4,%5,%6,%7},{%8,%9},{%0,%1,%2,%3};"
        : "+f"(c[0]), "+f"(c[1]), "+f"(c[2]), "+f"(c[3])
        : "r"(a[0]), "r"(a[1]), "r"(a[2]), "r"(a[3]), "r"(b[0]), "r"(b[1]));
}

__device__ __forceinline__ void split_store4(__nv_bfloat16* __restrict__ H,
                                             __nv_bfloat16* __restrict__ L,
                                             int base, float4 v)
{
    float xs[4] = {v.x, v.y, v.z, v.w};
#pragma unroll
    for (int i = 0; i < 4; i++) {
        __nv_bfloat16 h = __float2bfloat16(xs[i]);
        H[base + i] = h;
        L[base + i] = __float2bfloat16(xs[i] - __bfloat162float(h));
    }
}

// ---------------- tensor GEMM: C = alpha * A^T B (+ Cin) ----------------
// column-major. A: K x M (lda, k-contiguous), B: K x N (ldb). M,N mult of 128, K mult of 16.
__global__ __launch_bounds__(256) void tgemm_tn(
    const float* __restrict__ A, int lda, const float* __restrict__ B, int ldb,
    const float* __restrict__ Cin, float* __restrict__ Cout, int ldc,
    int K, float alpha, int upperOnly)
{
    int p0 = blockIdx.x * 128, q0 = blockIdx.y * 128;
    if (upperOnly && q0 < p0) return;
    __shared__ __nv_bfloat16 Ah[128 * PIT], Al[128 * PIT], Bh[128 * PIT], Bl[128 * PIT];
    int tid = threadIdx.x, lane = tid & 31, warp = tid >> 5;
    int wm = (warp >> 2) * 64, wn = (warp & 3) * 32;
    int g = lane >> 2, tg = lane & 3;
    float acc[4][4][4];
#pragma unroll
    for (int i = 0; i < 4; i++)
#pragma unroll
        for (int j = 0; j < 4; j++)
#pragma unroll
            for (int k = 0; k < 4; k++) acc[i][j][k] = 0.f;

    int arow = tid >> 2, akq = (tid & 3) * 4;
    const float* pA0 = A + (size_t)(p0 + arow) * lda + akq;
    const float* pA1 = A + (size_t)(p0 + arow + 64) * lda + akq;
    const float* pB0 = B + (size_t)(q0 + arow) * ldb + akq;
    const float* pB1 = B + (size_t)(q0 + arow + 64) * ldb + akq;
    float4 ra0 = *(const float4*)pA0;
    float4 ra1 = *(const float4*)pA1;
    float4 rb0 = *(const float4*)pB0;
    float4 rb1 = *(const float4*)pB1;

    for (int k0 = 0; k0 < K; k0 += 16) {
        split_store4(Ah, Al, arow * PIT + akq, ra0);
        split_store4(Ah, Al, (arow + 64) * PIT + akq, ra1);
        split_store4(Bh, Bl, arow * PIT + akq, rb0);
        split_store4(Bh, Bl, (arow + 64) * PIT + akq, rb1);
        __syncthreads();
        int kn = k0 + 16;
        if (kn < K) {
            ra0 = *(const float4*)(pA0 + kn);
            ra1 = *(const float4*)(pA1 + kn);
            rb0 = *(const float4*)(pB0 + kn);
            rb1 = *(const float4*)(pB1 + kn);
        }
        unsigned afh[4][4], afl[4][4], bfh[4][2], bfl[4][2];
#pragma unroll
        for (int mi = 0; mi < 4; mi++) {
            int r = (wm + mi * 16 + g) * PIT + 2 * tg;
            int r8 = r + 8 * PIT;
            afh[mi][0] = *(const unsigned*)&Ah[r];
            afh[mi][1] = *(const unsigned*)&Ah[r8];
            afh[mi][2] = *(const unsigned*)&Ah[r + 8];
            afh[mi][3] = *(const unsigned*)&Ah[r8 + 8];
            afl[mi][0] = *(const unsigned*)&Al[r];
            afl[mi][1] = *(const unsigned*)&Al[r8];
            afl[mi][2] = *(const unsigned*)&Al[r + 8];
            afl[mi][3] = *(const unsigned*)&Al[r8 + 8];
        }
#pragma unroll
        for (int ni = 0; ni < 4; ni++) {
            int r = (wn + ni * 8 + g) * PIT + 2 * tg;
            bfh[ni][0] = *(const unsigned*)&Bh[r];
            bfh[ni][1] = *(const unsigned*)&Bh[r + 8];
            bfl[ni][0] = *(const unsigned*)&Bl[r];
            bfl[ni][1] = *(const unsigned*)&Bl[r + 8];
        }
#pragma unroll
        for (int mi = 0; mi < 4; mi++)
#pragma unroll
            for (int ni = 0; ni < 4; ni++) {
                mma_bf16(acc[mi][ni], afh[mi], bfh[ni]);
                mma_bf16(acc[mi][ni], afh[mi], bfl[ni]);
                mma_bf16(acc[mi][ni], afl[mi], bfh[ni]);
            }
        __syncthreads();
    }
#pragma unroll
    for (int mi = 0; mi < 4; mi++)
#pragma unroll
        for (int ni = 0; ni < 4; ni++) {
            int p = p0 + wm + mi * 16 + g;
            int q = q0 + wn + ni * 8 + 2 * tg;
            float* c = acc[mi][ni];
            size_t o00 = (size_t)q * ldc + p;
            size_t o01 = (size_t)(q + 1) * ldc + p;
            float v00 = alpha * c[0], v01 = alpha * c[1];
            float v10 = alpha * c[2], v11 = alpha * c[3];
            if (Cin) { v00 += Cin[o00]; v01 += Cin[o01]; v10 += Cin[o00 + 8]; v11 += Cin[o01 + 8]; }
            Cout[o00] = v00; Cout[o01] = v01; Cout[o00 + 8] = v10; Cout[o01 + 8] = v11;
        }
}

// ---------------- tensor GEMM: C = gamma*(A*S) + alpha*X + beta*Y ----------------
// A: M x K col-major (m-contiguous, lda), S: K x N col-major (k-contiguous, lds).
__global__ __launch_bounds__(256) void tgemm_nn(
    const float* __restrict__ A, int lda, const float* __restrict__ S, int lds,
    const float* __restrict__ X, float alpha, const float* __restrict__ Y, float beta,
    float gamma, float* __restrict__ Cout, int ldc, int K, int triK)
{
    int i0 = blockIdx.x * 128, q0 = blockIdx.y * 128;
    int kmax = triK ? (q0 + 128) : K;
    if (kmax > K) kmax = K;
    __shared__ __nv_bfloat16 Ah[128 * PIT], Al[128 * PIT], Bh[128 * PIT], Bl[128 * PIT];
    int tid = threadIdx.x, lane = tid & 31, warp = tid >> 5;
    int wm = (warp >> 2) * 64, wn = (warp & 3) * 32;
    int g = lane >> 2, tg = lane & 3;
    float acc[4][4][4];
#pragma unroll
    for (int i = 0; i < 4; i++)
#pragma unroll
        for (int j = 0; j < 4; j++)
#pragma unroll
            for (int k = 0; k < 4; k++) acc[i][j][k] = 0.f;

    int kcol = tid >> 4, m4 = tid & 15;
    int arow = tid >> 2, akq = (tid & 3) * 4;
    const float* pS0 = S + (size_t)(q0 + arow) * lds + akq;
    const float* pS1 = S + (size_t)(q0 + arow + 64) * lds + akq;
    float4 ra0 = *(const float4*)(A + (size_t)kcol * lda + i0 + m4 * 4);
    float4 ra1 = *(const float4*)(A + (size_t)kcol * lda + i0 + 64 + m4 * 4);
    float4 rb0 = *(const float4*)pS0;
    float4 rb1 = *(const float4*)pS1;

    for (int k0 = 0; k0 < kmax; k0 += 16) {
        {
            float xs0[4] = {ra0.x, ra0.y, ra0.z, ra0.w};
            float xs1[4] = {ra1.x, ra1.y, ra1.z, ra1.w};
#pragma unroll
            for (int i = 0; i < 4; i++) {
                int r0 = (m4 * 4 + i) * PIT + kcol;
                int r1 = (m4 * 4 + 64 + i) * PIT + kcol;
                __nv_bfloat16 h0 = __float2bfloat16(xs0[i]);
                __nv_bfloat16 h1 = __float2bfloat16(xs1[i]);
                Ah[r0] = h0; Al[r0] = __float2bfloat16(xs0[i] - __bfloat162float(h0));
                Ah[r1] = h1; Al[r1] = __float2bfloat16(xs1[i] - __bfloat162float(h1));
            }
        }
        split_store4(Bh, Bl, arow * PIT + akq, rb0);
        split_store4(Bh, Bl, (arow + 64) * PIT + akq, rb1);
        __syncthreads();
        int kn = k0 + 16;
        if (kn < kmax) {
            ra0 = *(const float4*)(A + (size_t)(kn + kcol) * lda + i0 + m4 * 4);
            ra1 = *(const float4*)(A + (size_t)(kn + kcol) * lda + i0 + 64 + m4 * 4);
            rb0 = *(const float4*)(pS0 + kn);
            rb1 = *(const float4*)(pS1 + kn);
        }
        unsigned afh[4][4], afl[4][4], bfh[4][2], bfl[4][2];
#pragma unroll
        for (int mi = 0; mi < 4; mi++) {
            int r = (wm + mi * 16 + g) * PIT + 2 * tg;
            int r8 = r + 8 * PIT;
            afh[mi][0] = *(const unsigned*)&Ah[r];
            afh[mi][1] = *(const unsigned*)&Ah[r8];
            afh[mi][2] = *(const unsigned*)&Ah[r + 8];
            afh[mi][3] = *(const unsigned*)&Ah[r8 + 8];
            afl[mi][0] = *(const unsigned*)&Al[r];
            afl[mi][1] = *(const unsigned*)&Al[r8];
            afl[mi][2] = *(const unsigned*)&Al[r + 8];
            afl[mi][3] = *(const unsigned*)&Al[r8 + 8];
        }
#pragma unroll
        for (int ni = 0; ni < 4; ni++) {
            int r = (wn + ni * 8 + g) * PIT + 2 * tg;
            bfh[ni][0] = *(const unsigned*)&Bh[r];
            bfh[ni][1] = *(const unsigned*)&Bh[r + 8];
            bfl[ni][0] = *(const unsigned*)&Bl[r];
            bfl[ni][1] = *(const unsigned*)&Bl[r + 8];
        }
#pragma unroll
        for (int mi = 0; mi < 4; mi++)
#pragma unroll
            for (int ni = 0; ni < 4; ni++) {
                mma_bf16(acc[mi][ni], afh[mi], bfh[ni]);
                mma_bf16(acc[mi][ni], afh[mi], bfl[ni]);
                mma_bf16(acc[mi][ni], afl[mi], bfh[ni]);
            }
        __syncthreads();
    }
#pragma unroll
    for (int mi = 0; mi < 4; mi++)
#pragma unroll
        for (int ni = 0; ni < 4; ni++) {
            int p = i0 + wm + mi * 16 + g;
            int q = q0 + wn + ni * 8 + 2 * tg;
            float* c = acc[mi][ni];
            size_t o00 = (size_t)q * ldc + p;
            size_t o01 = (size_t)(q + 1) * ldc + p;
            float v00 = gamma * c[0], v01 = gamma * c[1];
            float v10 = gamma * c[2], v11 = gamma * c[3];
            if (X) { v00 += alpha * X[o00]; v01 += alpha * X[o01]; v10 += alpha * X[o00 + 8]; v11 += alpha * X[o01 + 8]; }
            if (Y) { v00 += beta * Y[o00]; v01 += beta * Y[o01]; v10 += beta * Y[o00 + 8]; v11 += beta * Y[o01 + 8]; }
            Cout[o00] = v00; Cout[o01] = v01; Cout[o00 + 8] = v10; Cout[o01 + 8] = v11;
        }
}

// ---------------- FFMA GEMM for the small Cholesky trailing updates ----------------
__global__ __launch_bounds__(256) void gemm_tn(
    const float* __restrict__ A, int lda, const float* __restrict__ B, int ldb,
    const float* __restrict__ Cin, float* __restrict__ Cout, int ldc,
    int K, float alpha, int upperOnly)
{
    int p0 = blockIdx.x * 64, q0 = blockIdx.y * 64;
    if (upperOnly && q0 < p0) return;
    __shared__ float As[16][68];
    __shared__ float Bs[16][68];
    int tid = threadIdx.x, tx = tid & 15, ty = tid >> 4;
    float acc[4][4];
#pragma unroll
    for (int a = 0; a < 4; a++)
#pragma unroll
        for (int b = 0; b < 4; b++) acc[a][b] = 0.f;
    for (int k0 = 0; k0 < K; k0 += 16) {
#pragma unroll
        for (int s2 = 0; s2 < 4; s2++) {
            int idx = tid + s2 * 256;
            int kk = idx & 15, pp = idx >> 4;
            As[kk][pp] = A[(size_t)(p0 + pp) * lda + (k0 + kk)];
            Bs[kk][pp] = B[(size_t)(q0 + pp) * ldb + (k0 + kk)];
        }
        __syncthreads();
#pragma unroll
        for (int kk = 0; kk < 16; kk++) {
            float4 av = *(const float4*)&As[kk][ty * 4];
            float4 bv = *(const float4*)&Bs[kk][tx * 4];
            float ar[4] = {av.x, av.y, av.z, av.w};
            float br[4] = {bv.x, bv.y, bv.z, bv.w};
#pragma unroll
            for (int a = 0; a < 4; a++)
#pragma unroll
                for (int b = 0; b < 4; b++)
                    acc[a][b] = fmaf(ar[a], br[b], acc[a][b]);
        }
        __syncthreads();
    }
#pragma unroll
    for (int a = 0; a < 4; a++)
#pragma unroll
        for (int b = 0; b < 4; b++) {
            int p = p0 + ty * 4 + a, q = q0 + tx * 4 + b;
            size_t o = (size_t)q * ldc + p;
            float v = alpha * acc[a][b];
            if (Cin) v += Cin[o];
            Cout[o] = v;
        }
}

// ---------------- small kernels ----------------
__global__ void symK(const float* __restrict__ in, float* __restrict__ outp) {
    int idx = blockIdx.x * 256 + threadIdx.x;
    int p = idx & (CDIM - 1), q = idx >> 11;
    outp[idx] = 0.5f * (in[idx] + in[(size_t)p * CDIM + q]);
}

__global__ void rowsqK() {
    int i = blockIdx.x * 256 + threadIdx.x;
    int q0 = blockIdx.y * (CDIM / 16);
    float acc = 0.f;
    for (int q = q0; q < q0 + CDIM / 16; q++) {
        float v = g_G[(size_t)q * RDIM + i];
        acc += v * v;
    }
    g_rowp[(size_t)blockIdx.y * RDIM + i] = acc;
}
__global__ void rowcombK() {
    int i = blockIdx.x * 256 + threadIdx.x;
    float s = 0.f;
    for (int ch = 0; ch < 16; ch++) s += g_rowp[(size_t)ch * RDIM + i];
    g_dL[i] = s / (float)CDIM;
}
__global__ void colsqK() {
    __shared__ float red[256];
    int q = blockIdx.x, tid = threadIdx.x;
    const float* col = g_G + (size_t)q * RDIM;
    float acc = 0.f;
    for (int i = tid; i < RDIM; i += 256) { float v = col[i]; acc += v * v; }
    red[tid] = acc; __syncthreads();
    for (int s = 128; s > 0; s >>= 1) { if (tid < s) red[tid] += red[tid + s]; __syncthreads(); }
    if (tid == 0) g_dR[q] = red[0] / (float)RDIM;
}

__device__ __forceinline__ float sigm(float x) { return 1.f / (1.f + expf(-x)); }

__global__ __launch_bounds__(256) void lstmK(
    int N, const float* __restrict__ diag,
    const float* __restrict__ h0, const float* __restrict__ c0,
    const float* __restrict__ Wih0, const float* __restrict__ Whh0,
    const float* __restrict__ bih0, const float* __restrict__ bhh0,
    const float* __restrict__ Wih1, const float* __restrict__ Whh1,
    const float* __restrict__ bih1, const float* __restrict__ bhh1,
    const float* __restrict__ LW, const float* __restrict__ Lb,
    float* __restrict__ raw, float* __restrict__ part)
{
    __shared__ float sWih0[80], sB0[80], sB1[80];
    __shared__ float sWhh0[1600], sWih1[1600], sWhh1[1600];
    __shared__ float sLW[HID];
    int tid = threadIdx.x;
    for (int k = tid; k < 80; k += 256) {
        sWih0[k] = Wih0[k];
        sB0[k] = bih0[k] + bhh0[k];
        sB1[k] = bih1[k] + bhh1[k];
    }
    for (int k = tid; k < 1600; k += 256) {
        sWhh0[k] = Whh0[k]; sWih1[k] = Wih1[k]; sWhh1[k] = Whh1[k];
    }
    if (tid < HID) sLW[tid] = LW[tid];
    __syncthreads();

    int n = blockIdx.x * 256 + tid;
    float d = diag[n];
    float x = logf(fabsf(d)) * 0.1f;
    x = fminf(fmaxf(x, -1.f), 1.f);

    float hp[HID], h1[HID];
    const float* h0p = h0 + (size_t)n * HID;
    const float* c0p = c0 + (size_t)n * HID;
#pragma unroll
    for (int j = 0; j < HID; j++) hp[j] = h0p[j];
    for (int jh = 0; jh < HID; jh++) {
        float gi = sB0[jh]      + sWih0[jh] * x;
        float gf = sB0[20 + jh] + sWih0[20 + jh] * x;
        float gg = sB0[40 + jh] + sWih0[40 + jh] * x;
        float go = sB0[60 + jh] + sWih0[60 + jh] * x;
#pragma unroll
        for (int j = 0; j < HID; j++) {
            float hv = hp[j];
            gi = fmaf(sWhh0[jh * 20 + j], hv, gi);
            gf = fmaf(sWhh0[(20 + jh) * 20 + j], hv, gf);
            gg = fmaf(sWhh0[(40 + jh) * 20 + j], hv, gg);
            go = fmaf(sWhh0[(60 + jh) * 20 + j], hv, go);
        }
        float cc = sigm(gf) * c0p[jh] + sigm(gi) * tanhf(gg);
        h1[jh] = sigm(go) * tanhf(cc);
    }
    const float* h1p = h0 + (size_t)N * HID + (size_t)n * HID;
    const float* c1p = c0 + (size_t)N * HID + (size_t)n * HID;
    float hb[HID];
#pragma unroll
    for (int j = 0; j < HID; j++) hb[j] = h1p[j];
    float o = 0.f;
    for (int jh = 0; jh < HID; jh++) {
        float gi = sB1[jh], gf = sB1[20 + jh], gg = sB1[40 + jh], go = sB1[60 + jh];
#pragma unroll
        for (int j = 0; j < HID; j++) {
            float a = h1[j], b = hb[j];
            gi = fmaf(sWih1[jh * 20 + j], a, fmaf(sWhh1[jh * 20 + j], b, gi));
            gf = fmaf(sWih1[(20 + jh) * 20 + j], a, fmaf(sWhh1[(20 + jh) * 20 + j], b, gf));
            gg = fmaf(sWih1[(40 + jh) * 20 + j], a, fmaf(sWhh1[(40 + jh) * 20 + j], b, gg));
            go = fmaf(sWih1[(60 + jh) * 20 + j], a, fmaf(sWhh1[(60 + jh) * 20 + j], b, go));
        }
        float cc = sigm(gf) * c1p[jh] + sigm(gi) * tanhf(gg);
        float h2 = sigm(go) * tanhf(cc);
        o = fmaf(sLW[jh], h2, o);
    }
    float val = (o + Lb[0]) * 0.1f;
    raw[n] = val;

    __shared__ float red[256];
    red[tid] = val; __syncthreads();
    for (int s = 128; s > 0; s >>= 1) { if (tid < s) red[tid] += red[tid + s]; __syncthreads(); }
    if (tid == 0) part[blockIdx.x] = red[0];
}

__global__ void meansK() {
    if (threadIdx.x == 0) {
        float s = 0.f; for (int i = 0; i < 32; i++) s += g_partL[i];
        g_means[0] = s / (float)RDIM;
        float t = 0.f; for (int i = 0; i < 8; i++) t += g_partR[i];
        g_means[1] = t / (float)CDIM;
    }
}

__global__ void applyK(const float* __restrict__ raw, const float* __restrict__ before,
                       int mi, float* __restrict__ outv) {
    int i = blockIdx.x * 256 + threadIdx.x;
    outv[i] = fmaxf(raw[i] - g_means[mi] + 1.0f, before[i]);
}

__global__ void p0K() {
    size_t idx = (size_t)blockIdx.x * 256 + threadIdx.x;
    int i = (int)(idx & (RDIM - 1));
    int q = (int)(idx >> 13);
    g_P0[idx] = g_Lv[i] * g_G[idx] * g_Rv[q];
}

// ---------------- Cholesky / triangular inverse ----------------
__global__ void cholDiagK(int k0) {
    __shared__ float S[64][65];
    int t = threadIdx.x;
    for (int e = t; e < 4096; e += 64) {
        int a = e & 63, b = e >> 6;
        S[a][b] = g_Gram[(size_t)(k0 + b) * CDIM + (k0 + a)];
    }
    __syncthreads();
    for (int j = 0; j < 64; j++) {
        if (t == 0) S[j][j] = sqrtf(S[j][j]);
        __syncthreads();
        float rjj = S[j][j];
        if (t > j) S[j][t] /= rjj;
        __syncthreads();
        if (t > j) {
            float sjt = S[j][t];
            for (int a = j + 1; a <= t; a++) S[a][t] -= S[j][a] * sjt;
        }
        __syncthreads();
    }
    for (int e = t; e < 4096; e += 64) {
        int a = e & 63, b = e >> 6;
        if (a <= b) g_Gram[(size_t)(k0 + b) * CDIM + (k0 + a)] = S[a][b];
    }
}

__global__ void cholTrsmK(int k0) {
    __shared__ float Rkk[64][65];
    __shared__ float Xs[64][65];
    int t = threadIdx.x;
    int qb = k0 + 64 + blockIdx.x * 64;
    for (int e = t; e < 4096; e += 64) {
        int a = e & 63, b = e >> 6;
        Rkk[a][b] = g_Gram[(size_t)(k0 + b) * CDIM + (k0 + a)];
        Xs[a][b]  = g_Gram[(size_t)(qb + b) * CDIM + (k0 + a)];
    }
    __syncthreads();
    for (int a = 0; a < 64; a++) {
        float sum = 0.f;
        for (int b = 0; b < a; b++) sum = fmaf(Rkk[b][a], Xs[b][t], sum);
        Xs[a][t] = (Xs[a][t] - sum) / Rkk[a][a];
    }
    __syncthreads();
    for (int e = t; e < 4096; e += 64) {
        int a = e & 63, b = e >> 6;
        g_Gram[(size_t)(qb + b) * CDIM + (k0 + a)] = Xs[a][b];
    }
}

__global__ void invDiagK() {
    int k0 = blockIdx.x * 64;
    __shared__ float U[64][65];
    __shared__ float Xs[64][65];
    int t = threadIdx.x;
    for (int e = t; e < 4096; e += 64) {
        int a = e & 63, b = e >> 6;
        U[a][b] = (a <= b) ? g_Gram[(size_t)(k0 + b) * CDIM + (k0 + a)] : 0.f;
        Xs[a][b] = 0.f;
    }
    __syncthreads();
    for (int a = 63; a >= 0; a--) {
        if (a <= t) {
            float sum = (a == t) ? 1.f : 0.f;
            for (int b = a + 1; b <= t; b++) sum = fmaf(-U[a][b], Xs[b][t], sum);
            Xs[a][t] = sum / U[a][a];
        }
    }
    __syncthreads();
    for (int e = t; e < 4096; e += 64) {
        int a = e & 63, b = e >> 6;
        g_Rinv[(size_t)(k0 + b) * CDIM + (k0 + a)] = Xs[a][b];
    }
}

__global__ __launch_bounds__(256) void invOffK(int d) {
    int i = blockIdx.x, j = i + d;
    __shared__ float As[16][68];
    __shared__ float Bs[16][68];
    __shared__ float Ws[64][68];
    __shared__ float Us[64][68];
    int tid = threadIdx.x, tx = tid & 15, ty = tid >> 4;
    float acc[4][4];
#pragma unroll
    for (int a = 0; a < 4; a++)
#pragma unroll
        for (int b = 0; b < 4; b++) acc[a][b] = 0.f;
    for (int kb = i + 1; kb <= j; kb++) {
        for (int k16 = 0; k16 < 64; k16 += 16) {
#pragma unroll
            for (int s2 = 0; s2 < 4; s2++) {
                int idx = tid + s2 * 256;
                int pp = idx & 63, kk = idx >> 6;
                As[kk][pp] = g_Gram[(size_t)(kb * 64 + k16 + kk) * CDIM + (i * 64 + pp)];
                int kk2 = idx & 15, qq = idx >> 4;
                Bs[kk2][qq] = g_Rinv[(size_t)(j * 64 + qq) * CDIM + (kb * 64 + k16 + kk2)];
            }
            __syncthreads();
#pragma unroll
            for (int kk = 0; kk < 16; kk++) {
                float4 av = *(const float4*)&As[kk][ty * 4];
                float4 bv = *(const float4*)&Bs[kk][tx * 4];
                float ar[4] = {av.x, av.y, av.z, av.w};
                float br[4] = {bv.x, bv.y, bv.z, bv.w};
#pragma unroll
                for (int a = 0; a < 4; a++)
#pragma unroll
                    for (int b = 0; b < 4; b++)
                        acc[a][b] = fmaf(ar[a], br[b], acc[a][b]);
            }
            __syncthreads();
        }
    }
#pragma unroll
    for (int a = 0; a < 4; a++)
#pragma unroll
        for (int b = 0; b < 4; b++) Ws[ty * 4 + a][tx * 4 + b] = acc[a][b];
    for (int e = tid; e < 4096; e += 256) {
        int aa = e & 63, bb = e >> 6;
        Us[aa][bb] = g_Rinv[(size_t)(i * 64 + bb) * CDIM + (i * 64 + aa)];
    }
    __syncthreads();
#pragma unroll
    for (int a = 0; a < 4; a++) {
        int p = ty * 4 + a;
#pragma unroll
        for (int b = 0; b < 4; b++) {
            int q = tx * 4 + b;
            float s = 0.f;
            for (int m = p; m < 64; m++) s = fmaf(Us[p][m], Ws[m][q], s);
            g_Rinv[(size_t)(j * 64 + q) * CDIM + (i * 64 + p)] = -s;
        }
    }
}

extern "C" void kernel_launch(void* const* d_in, const int* in_sizes, int n_in,
                              void* d_out, int out_size) {
    const float* s   = (const float*)d_in[0];
    const float* sg  = (const float*)d_in[1];
    const float* Lh0 = (const float*)d_in[2];
    const float* Lc0 = (const float*)d_in[3];
    const float* Rh0 = (const float*)d_in[4];
    const float* Rc0 = (const float*)d_in[5];
    const float* Lbef = (const float*)d_in[6];
    const float* Rbef = (const float*)d_in[7];
    const float* Wih0 = (const float*)d_in[8];
    const float* Whh0 = (const float*)d_in[9];
    const float* bih0 = (const float*)d_in[10];
    const float* bhh0 = (const float*)d_in[11];
    const float* Wih1 = (const float*)d_in[12];
    const float* Whh1 = (const float*)d_in[13];
    const float* bih1 = (const float*)d_in[14];
    const float* bhh1 = (const float*)d_in[15];
    const float* LW = (const float*)d_in[16];
    const float* Lb = (const float*)d_in[17];
    const float* RW = (const float*)d_in[18];
    const float* Rb = (const float*)d_in[19];
    float* out = (float*)d_out;

    float *gG, *gP0, *gB, *gA, *gAs, *gGram, *gRinv;
    float *gdL, *gdR, *glraw, *grraw, *gpartL, *gpartR, *gLv, *gRv;
    cudaGetSymbolAddress((void**)&gG, g_G);
    cudaGetSymbolAddress((void**)&gP0, g_P0);
    cudaGetSymbolAddress((void**)&gB, g_B);
    cudaGetSymbolAddress((void**)&gA, g_A);
    cudaGetSymbolAddress((void**)&gAs, g_As);
    cudaGetSymbolAddress((void**)&gGram, g_Gram);
    cudaGetSymbolAddress((void**)&gRinv, g_Rinv);
    cudaGetSymbolAddress((void**)&gdL, g_dL);
    cudaGetSymbolAddress((void**)&gdR, g_dR);
    cudaGetSymbolAddress((void**)&glraw, g_lraw);
    cudaGetSymbolAddress((void**)&grraw, g_rraw);
    cudaGetSymbolAddress((void**)&gpartL, g_partL);
    cudaGetSymbolAddress((void**)&gpartR, g_partR);
    cudaGetSymbolAddress((void**)&gLv, g_Lv);
    cudaGetSymbolAddress((void**)&gRv, g_Rv);

    // A = M^T * (0.1*Mgrad)
    tgemm_tn<<<dim3(16, 16), 256>>>(s, RDIM, sg, RDIM, nullptr, gA, CDIM, RDIM, 0.1f, 0);
    symK<<<CDIM * CDIM / 256, 256>>>(gA, gAs);
    // G = 0.1*Mgrad - M*As
    tgemm_nn<<<dim3(64, 16), 256>>>(s, RDIM, gAs, CDIM, sg, 0.1f, nullptr, 0.f, -1.f, gG, RDIM, CDIM, 0);
    // Gram diagonals
    rowsqK<<<dim3(32, 16), 256>>>();
    rowcombK<<<32, 256>>>();
    colsqK<<<CDIM, 256>>>();
    // LSTMs
    lstmK<<<32, 256>>>(RDIM, gdL, Lh0, Lc0, Wih0, Whh0, bih0, bhh0, Wih1, Whh1, bih1, bhh1, LW, Lb, glraw, gpartL);
    lstmK<<<8, 256>>>(CDIM, gdR, Rh0, Rc0, Wih0, Whh0, bih0, bhh0, Wih1, Whh1, bih1, bhh1, RW, Rb, grraw, gpartR);
    meansK<<<1, 32>>>();
    applyK<<<32, 256>>>(glraw, Lbef, 0, gLv);
    applyK<<<8, 256>>>(grraw, Rbef, 1, gRv);
    // P0 = Lv . G . Rv
    p0K<<<(unsigned)((size_t)RDIM * CDIM / 256), 256>>>();
    // A2 = M^T*P0 ; As2 = sym ; B = M*As2 + s - P0
    tgemm_tn<<<dim3(16, 16), 256>>>(s, RDIM, gP0, RDIM, nullptr, gA, CDIM, RDIM, 1.f, 0);
    symK<<<CDIM * CDIM / 256, 256>>>(gA, gAs);
    tgemm_nn<<<dim3(64, 16), 256>>>(s, RDIM, gAs, CDIM, s, 1.f, gP0, -1.f, 1.f, gB, RDIM, CDIM, 0);
    // Gram = B^T B (upper)
    tgemm_tn<<<dim3(16, 16), 256>>>(gB, RDIM, gB, RDIM, nullptr, gGram, CDIM, RDIM, 1.f, 1);
    // blocked Cholesky
    for (int k = 0; k < NBLK; k++) {
        cholDiagK<<<1, 64>>>(k * 64);
        int nb = NBLK - 1 - k;
        if (nb > 0) {
            cholTrsmK<<<nb, 64>>>(k * 64);
            int r0 = (k + 1) * 64;
            const float* panel = gGram + (size_t)r0 * CDIM + k * 64;
            float* base = gGram + (size_t)r0 * CDIM + r0;
            gemm_tn<<<dim3(nb, nb), 256>>>(panel, CDIM, panel, CDIM, base, base, CDIM, 64, -1.f, 1);
        }
    }
    // Rinv
    invDiagK<<<NBLK, 64>>>();
    for (int d = 1; d < NBLK; d++) invOffK<<<NBLK - d, 256>>>(d);
    // Q = B * Rinv -> out
    tgemm_nn<<<dim3(64, 16), 256>>>(gB, RDIM, gRinv, CDIM, nullptr, 0.f, nullptr, 0.f, 1.f, out, RDIM, CDIM, 1);
}

// round 4
// speedup vs baseline: 1.8751x; 1.2717x over previous
#include <cuda_runtime.h>
#include <cuda_bf16.h>
#include <math.h>

#define RDIM 8192
#define CDIM 2048
#define HID 20
#define NBLK 32
#define PIT 20   // SMEM row pitch in bf16 halves (mult of 4; 10-word stride -> conflict-light)

// ---------------- device scratch ----------------
__device__ float g_G   [(size_t)RDIM * CDIM];
__device__ float g_P0  [(size_t)RDIM * CDIM];
__device__ float g_B   [(size_t)RDIM * CDIM];
__device__ float g_A   [(size_t)CDIM * CDIM];
__device__ float g_As  [(size_t)CDIM * CDIM];
__device__ float g_Gram[(size_t)CDIM * CDIM];
__device__ float g_Rinv[(size_t)CDIM * CDIM];
__device__ float g_T   [(size_t)1024 * 1024];
__device__ float g_rowp[16 * (size_t)RDIM];
__device__ float g_dL[RDIM];
__device__ float g_dR[CDIM];
__device__ float g_lraw[RDIM];
__device__ float g_rraw[CDIM];
__device__ float g_partL[32];
__device__ float g_partR[8];
__device__ float g_means[2];
__device__ float g_Lv[RDIM];
__device__ float g_Rv[CDIM];

// ---------------- tensor-core helpers ----------------
__device__ __forceinline__ void mma_bf16(float* c, const unsigned* a, const unsigned* b) {
    asm volatile(
        "mma.sync.aligned.m16n8k16.row.col.f32.bf16.bf16.f32 "
        "{%0,%1,%2,%3},{%4,%5,%6,%7},{%8,%9},{%0,%1,%2,%3};"
        : "+f"(c[0]), "+f"(c[1]), "+f"(c[2]), "+f"(c[3])
        : "r"(a[0]), "r"(a[1]), "r"(a[2]), "r"(a[3]), "r"(b[0]), "r"(b[1]));
}

__device__ __forceinline__ unsigned pack_bf2(__nv_bfloat16 a, __nv_bfloat16 b) {
    return (unsigned)__bfloat16_as_ushort(a) | ((unsigned)__bfloat16_as_ushort(b) << 16);
}

__device__ __forceinline__ void split4(const float* x, uint2& h, uint2& l) {
    __nv_bfloat16 h0 = __float2bfloat16(x[0]);
    __nv_bfloat16 h1 = __float2bfloat16(x[1]);
    __nv_bfloat16 h2 = __float2bfloat16(x[2]);
    __nv_bfloat16 h3 = __float2bfloat16(x[3]);
    h.x = pack_bf2(h0, h1);
    h.y = pack_bf2(h2, h3);
    l.x = pack_bf2(__float2bfloat16(x[0] - __bfloat162float(h0)),
                   __float2bfloat16(x[1] - __bfloat162float(h1)));
    l.y = pack_bf2(__float2bfloat16(x[2] - __bfloat162float(h2)),
                   __float2bfloat16(x[3] - __bfloat162float(h3)));
}

// ---------------- tensor GEMM: C = alpha * A^T B (+ Cin) ----------------
// column-major. A: K x M (lda, k-contiguous), B: K x N (ldb). M,N mult of 128, K mult of 16.
__global__ __launch_bounds__(256) void tgemm_tn(
    const float* __restrict__ A, int lda, const float* __restrict__ B, int ldb,
    const float* __restrict__ Cin, float* __restrict__ Cout, int ldc,
    int K, float alpha, int upperOnly)
{
    int p0 = blockIdx.x * 128, q0 = blockIdx.y * 128;
    if (upperOnly && q0 < p0) return;
    __shared__ __align__(16) __nv_bfloat16 Ah[128 * PIT], Al[128 * PIT], Bh[128 * PIT], Bl[128 * PIT];
    int tid = threadIdx.x, lane = tid & 31, warp = tid >> 5;
    int wm = (warp >> 2) * 64, wn = (warp & 3) * 32;
    int g = lane >> 2, tg = lane & 3;
    float acc[4][4][4];
#pragma unroll
    for (int i = 0; i < 4; i++)
#pragma unroll
        for (int j = 0; j < 4; j++)
#pragma unroll
            for (int k = 0; k < 4; k++) acc[i][j][k] = 0.f;

    int arow = tid >> 2, akq = (tid & 3) * 4;
    const float* pA0 = A + (size_t)(p0 + arow) * lda + akq;
    const float* pA1 = A + (size_t)(p0 + arow + 64) * lda + akq;
    const float* pB0 = B + (size_t)(q0 + arow) * ldb + akq;
    const float* pB1 = B + (size_t)(q0 + arow + 64) * ldb + akq;
    float4 ra0 = *(const float4*)pA0;
    float4 ra1 = *(const float4*)pA1;
    float4 rb0 = *(const float4*)pB0;
    float4 rb1 = *(const float4*)pB1;

    for (int k0 = 0; k0 < K; k0 += 16) {
        uint2 h, l;
        split4((const float*)&ra0, h, l);
        *(uint2*)&Ah[arow * PIT + akq] = h; *(uint2*)&Al[arow * PIT + akq] = l;
        split4((const float*)&ra1, h, l);
        *(uint2*)&Ah[(arow + 64) * PIT + akq] = h; *(uint2*)&Al[(arow + 64) * PIT + akq] = l;
        split4((const float*)&rb0, h, l);
        *(uint2*)&Bh[arow * PIT + akq] = h; *(uint2*)&Bl[arow * PIT + akq] = l;
        split4((const float*)&rb1, h, l);
        *(uint2*)&Bh[(arow + 64) * PIT + akq] = h; *(uint2*)&Bl[(arow + 64) * PIT + akq] = l;
        __syncthreads();
        int kn = k0 + 16;
        if (kn < K) {
            ra0 = *(const float4*)(pA0 + kn);
            ra1 = *(const float4*)(pA1 + kn);
            rb0 = *(const float4*)(pB0 + kn);
            rb1 = *(const float4*)(pB1 + kn);
        }
        unsigned afh[4][4], afl[4][4], bfh[4][2], bfl[4][2];
#pragma unroll
        for (int mi = 0; mi < 4; mi++) {
            int r = (wm + mi * 16 + g) * PIT + 2 * tg;
            int r8 = r + 8 * PIT;
            afh[mi][0] = *(const unsigned*)&Ah[r];
            afh[mi][1] = *(const unsigned*)&Ah[r8];
            afh[mi][2] = *(const unsigned*)&Ah[r + 8];
            afh[mi][3] = *(const unsigned*)&Ah[r8 + 8];
            afl[mi][0] = *(const unsigned*)&Al[r];
            afl[mi][1] = *(const unsigned*)&Al[r8];
            afl[mi][2] = *(const unsigned*)&Al[r + 8];
            afl[mi][3] = *(const unsigned*)&Al[r8 + 8];
        }
#pragma unroll
        for (int ni = 0; ni < 4; ni++) {
            int r = (wn + ni * 8 + g) * PIT + 2 * tg;
            bfh[ni][0] = *(const unsigned*)&Bh[r];
            bfh[ni][1] = *(const unsigned*)&Bh[r + 8];
            bfl[ni][0] = *(const unsigned*)&Bl[r];
            bfl[ni][1] = *(const unsigned*)&Bl[r + 8];
        }
#pragma unroll
        for (int mi = 0; mi < 4; mi++)
#pragma unroll
            for (int ni = 0; ni < 4; ni++) {
                mma_bf16(acc[mi][ni], afh[mi], bfh[ni]);
                mma_bf16(acc[mi][ni], afh[mi], bfl[ni]);
                mma_bf16(acc[mi][ni], afl[mi], bfh[ni]);
            }
        __syncthreads();
    }
#pragma unroll
    for (int mi = 0; mi < 4; mi++)
#pragma unroll
        for (int ni = 0; ni < 4; ni++) {
            int p = p0 + wm + mi * 16 + g;
            int q = q0 + wn + ni * 8 + 2 * tg;
            float* c = acc[mi][ni];
            size_t o00 = (size_t)q * ldc + p;
            size_t o01 = (size_t)(q + 1) * ldc + p;
            float v00 = alpha * c[0], v01 = alpha * c[1];
            float v10 = alpha * c[2], v11 = alpha * c[3];
            if (Cin) { v00 += Cin[o00]; v01 += Cin[o01]; v10 += Cin[o00 + 8]; v11 += Cin[o01 + 8]; }
            Cout[o00] = v00; Cout[o01] = v01; Cout[o00 + 8] = v10; Cout[o01 + 8] = v11;
        }
}

// ---------------- tensor GEMM: C = gamma*(A*S) + alpha*X + beta*Y ----------------
// A: M x K col-major (m-contiguous, lda), S: K x N col-major (k-contiguous, lds).
__global__ __launch_bounds__(256) void tgemm_nn(
    const float* __restrict__ A, int lda, const float* __restrict__ S, int lds,
    const float* __restrict__ X, float alpha, const float* __restrict__ Y, float beta,
    float gamma, float* __restrict__ Cout, int ldc, int K, int triK)
{
    int i0 = blockIdx.x * 128, q0 = blockIdx.y * 128;
    int kmax = triK ? (q0 + 128) : K;
    if (kmax > K) kmax = K;
    __shared__ __align__(16) __nv_bfloat16 Ah[128 * PIT], Al[128 * PIT], Bh[128 * PIT], Bl[128 * PIT];
    int tid = threadIdx.x, lane = tid & 31, warp = tid >> 5;
    int wm = (warp >> 2) * 64, wn = (warp & 3) * 32;
    int g = lane >> 2, tg = lane & 3;
    float acc[4][4][4];
#pragma unroll
    for (int i = 0; i < 4; i++)
#pragma unroll
        for (int j = 0; j < 4; j++)
#pragma unroll
            for (int k = 0; k < 4; k++) acc[i][j][k] = 0.f;

    // A staging: thread -> m row (tid>>1), 8 consecutive k ((tid&1)*8)
    int m = tid >> 1, kh = (tid & 1) * 8;
    int arow = tid >> 2, akq = (tid & 3) * 4;
    const float* pS0 = S + (size_t)(q0 + arow) * lds + akq;
    const float* pS1 = S + (size_t)(q0 + arow + 64) * lds + akq;
    float ra[8];
#pragma unroll
    for (int j = 0; j < 8; j++) ra[j] = A[(size_t)(kh + j) * lda + i0 + m];
    float4 rb0 = *(const float4*)pS0;
    float4 rb1 = *(const float4*)pS1;

    for (int k0 = 0; k0 < kmax; k0 += 16) {
        uint2 h, l;
        split4(ra, h, l);
        *(uint2*)&Ah[m * PIT + kh] = h; *(uint2*)&Al[m * PIT + kh] = l;
        split4(ra + 4, h, l);
        *(uint2*)&Ah[m * PIT + kh + 4] = h; *(uint2*)&Al[m * PIT + kh + 4] = l;
        split4((const float*)&rb0, h, l);
        *(uint2*)&Bh[arow * PIT + akq] = h; *(uint2*)&Bl[arow * PIT + akq] = l;
        split4((const float*)&rb1, h, l);
        *(uint2*)&Bh[(arow + 64) * PIT + akq] = h; *(uint2*)&Bl[(arow + 64) * PIT + akq] = l;
        __syncthreads();
        int kn = k0 + 16;
        if (kn < kmax) {
#pragma unroll
            for (int j = 0; j < 8; j++) ra[j] = A[(size_t)(kn + kh + j) * lda + i0 + m];
            rb0 = *(const float4*)(pS0 + kn);
            rb1 = *(const float4*)(pS1 + kn);
        }
        unsigned afh[4][4], afl[4][4], bfh[4][2], bfl[4][2];
#pragma unroll
        for (int mi = 0; mi < 4; mi++) {
            int r = (wm + mi * 16 + g) * PIT + 2 * tg;
            int r8 = r + 8 * PIT;
            afh[mi][0] = *(const unsigned*)&Ah[r];
            afh[mi][1] = *(const unsigned*)&Ah[r8];
            afh[mi][2] = *(const unsigned*)&Ah[r + 8];
            afh[mi][3] = *(const unsigned*)&Ah[r8 + 8];
            afl[mi][0] = *(const unsigned*)&Al[r];
            afl[mi][1] = *(const unsigned*)&Al[r8];
            afl[mi][2] = *(const unsigned*)&Al[r + 8];
            afl[mi][3] = *(const unsigned*)&Al[r8 + 8];
        }
#pragma unroll
        for (int ni = 0; ni < 4; ni++) {
            int r = (wn + ni * 8 + g) * PIT + 2 * tg;
            bfh[ni][0] = *(const unsigned*)&Bh[r];
            bfh[ni][1] = *(const unsigned*)&Bh[r + 8];
            bfl[ni][0] = *(const unsigned*)&Bl[r];
            bfl[ni][1] = *(const unsigned*)&Bl[r + 8];
        }
#pragma unroll
        for (int mi = 0; mi < 4; mi++)
#pragma unroll
            for (int ni = 0; ni < 4; ni++) {
                mma_bf16(acc[mi][ni], afh[mi], bfh[ni]);
                mma_bf16(acc[mi][ni], afh[mi], bfl[ni]);
                mma_bf16(acc[mi][ni], afl[mi], bfh[ni]);
            }
        __syncthreads();
    }
#pragma unroll
    for (int mi = 0; mi < 4; mi++)
#pragma unroll
        for (int ni = 0; ni < 4; ni++) {
            int p = i0 + wm + mi * 16 + g;
            int q = q0 + wn + ni * 8 + 2 * tg;
            float* c = acc[mi][ni];
            size_t o00 = (size_t)q * ldc + p;
            size_t o01 = (size_t)(q + 1) * ldc + p;
            float v00 = gamma * c[0], v01 = gamma * c[1];
            float v10 = gamma * c[2], v11 = gamma * c[3];
            if (X) { v00 += alpha * X[o00]; v01 += alpha * X[o01]; v10 += alpha * X[o00 + 8]; v11 += alpha * X[o01 + 8]; }
            if (Y) { v00 += beta * Y[o00]; v01 += beta * Y[o01]; v10 += beta * Y[o00 + 8]; v11 += beta * Y[o01 + 8]; }
            Cout[o00] = v00; Cout[o01] = v01; Cout[o00 + 8] = v10; Cout[o01 + 8] = v11;
        }
}

// ---------------- FFMA GEMM (T^T x B) for Cholesky trailing updates ----------------
__global__ __launch_bounds__(256) void gemm_tn(
    const float* __restrict__ A, int lda, const float* __restrict__ B, int ldb,
    const float* __restrict__ Cin, float* __restrict__ Cout, int ldc,
    int K, float alpha, int upperOnly)
{
    int p0 = blockIdx.x * 64, q0 = blockIdx.y * 64;
    if (upperOnly && q0 < p0) return;
    __shared__ float As[16][68];
    __shared__ float Bs[16][68];
    int tid = threadIdx.x, tx = tid & 15, ty = tid >> 4;
    float acc[4][4];
#pragma unroll
    for (int a = 0; a < 4; a++)
#pragma unroll
        for (int b = 0; b < 4; b++) acc[a][b] = 0.f;
    for (int k0 = 0; k0 < K; k0 += 16) {
#pragma unroll
        for (int s2 = 0; s2 < 4; s2++) {
            int idx = tid + s2 * 256;
            int kk = idx & 15, pp = idx >> 4;
            As[kk][pp] = A[(size_t)(p0 + pp) * lda + (k0 + kk)];
            Bs[kk][pp] = B[(size_t)(q0 + pp) * ldb + (k0 + kk)];
        }
        __syncthreads();
#pragma unroll
        for (int kk = 0; kk < 16; kk++) {
            float4 av = *(const float4*)&As[kk][ty * 4];
            float4 bv = *(const float4*)&Bs[kk][tx * 4];
            float ar[4] = {av.x, av.y, av.z, av.w};
            float br[4] = {bv.x, bv.y, bv.z, bv.w};
#pragma unroll
            for (int a = 0; a < 4; a++)
#pragma unroll
                for (int b = 0; b < 4; b++)
                    acc[a][b] = fmaf(ar[a], br[b], acc[a][b]);
        }
        __syncthreads();
    }
#pragma unroll
    for (int a = 0; a < 4; a++)
#pragma unroll
        for (int b = 0; b < 4; b++) {
            int p = p0 + ty * 4 + a, q = q0 + tx * 4 + b;
            size_t o = (size_t)q * ldc + p;
            float v = alpha * acc[a][b];
            if (Cin) v += Cin[o];
            Cout[o] = v;
        }
}

// ---------------- batched FFMA NN GEMM for recursive triangular inverse ----------------
// per pair z: C = sgn * A*B. A: b x b col-major (lda), B: b x b (ldb), C (ldc).
__global__ __launch_bounds__(256) void gemm_nn_b(
    const float* __restrict__ A, long long sA, int lda,
    const float* __restrict__ B, long long sB, int ldb,
    float* __restrict__ C, long long sC, int ldc, int K, float sgn)
{
    const float* Ap = A + (size_t)blockIdx.z * sA;
    const float* Bp = B + (size_t)blockIdx.z * sB;
    float* Cp = C + (size_t)blockIdx.z * sC;
    int i0 = blockIdx.x * 64, q0 = blockIdx.y * 64;
    __shared__ float As[16][68];
    __shared__ float Bs[16][68];
    int tid = threadIdx.x, tx = tid & 15, ty = tid >> 4;
    float acc[4][4];
#pragma unroll
    for (int a = 0; a < 4; a++)
#pragma unroll
        for (int b = 0; b < 4; b++) acc[a][b] = 0.f;
    for (int k0 = 0; k0 < K; k0 += 16) {
#pragma unroll
        for (int s2 = 0; s2 < 4; s2++) {
            int idx = tid + s2 * 256;
            int ii = idx & 63, kk = idx >> 6;
            As[kk][ii] = Ap[(size_t)(k0 + kk) * lda + (i0 + ii)];
            int kk2 = idx & 15, qq = idx >> 4;
            Bs[kk2][qq] = Bp[(size_t)(q0 + qq) * ldb + (k0 + kk2)];
        }
        __syncthreads();
#pragma unroll
        for (int kk = 0; kk < 16; kk++) {
            float4 av = *(const float4*)&As[kk][ty * 4];
            float4 bv = *(const float4*)&Bs[kk][tx * 4];
            float ar[4] = {av.x, av.y, av.z, av.w};
            float br[4] = {bv.x, bv.y, bv.z, bv.w};
#pragma unroll
            for (int a = 0; a < 4; a++)
#pragma unroll
                for (int b = 0; b < 4; b++)
                    acc[a][b] = fmaf(ar[a], br[b], acc[a][b]);
        }
        __syncthreads();
    }
#pragma unroll
    for (int a = 0; a < 4; a++)
#pragma unroll
        for (int b = 0; b < 4; b++) {
            int p = i0 + ty * 4 + a, q = q0 + tx * 4 + b;
            Cp[(size_t)q * ldc + p] = sgn * acc[a][b];
        }
}

// ---------------- small kernels ----------------
__global__ void zeroBufK(float* p) { p[(size_t)blockIdx.x * 256 + threadIdx.x] = 0.f; }

__global__ void symK(const float* __restrict__ in, float* __restrict__ outp) {
    int idx = blockIdx.x * 256 + threadIdx.x;
    int p = idx & (CDIM - 1), q = idx >> 11;
    outp[idx] = 0.5f * (in[idx] + in[(size_t)p * CDIM + q]);
}

__global__ void rowsqK() {
    int i = blockIdx.x * 256 + threadIdx.x;
    int q0 = blockIdx.y * (CDIM / 16);
    float acc = 0.f;
    for (int q = q0; q < q0 + CDIM / 16; q++) {
        float v = g_G[(size_t)q * RDIM + i];
        acc += v * v;
    }
    g_rowp[(size_t)blockIdx.y * RDIM + i] = acc;
}
__global__ void rowcombK() {
    int i = blockIdx.x * 256 + threadIdx.x;
    float s = 0.f;
    for (int ch = 0; ch < 16; ch++) s += g_rowp[(size_t)ch * RDIM + i];
    g_dL[i] = s / (float)CDIM;
}
__global__ void colsqK() {
    __shared__ float red[256];
    int q = blockIdx.x, tid = threadIdx.x;
    const float* col = g_G + (size_t)q * RDIM;
    float acc = 0.f;
    for (int i = tid; i < RDIM; i += 256) { float v = col[i]; acc += v * v; }
    red[tid] = acc; __syncthreads();
    for (int s = 128; s > 0; s >>= 1) { if (tid < s) red[tid] += red[tid + s]; __syncthreads(); }
    if (tid == 0) g_dR[q] = red[0] / (float)RDIM;
}

__device__ __forceinline__ float sigm(float x) { return 1.f / (1.f + expf(-x)); }

__global__ __launch_bounds__(256) void lstmK(
    int N, const float* __restrict__ diag,
    const float* __restrict__ h0, const float* __restrict__ c0,
    const float* __restrict__ Wih0, const float* __restrict__ Whh0,
    const float* __restrict__ bih0, const float* __restrict__ bhh0,
    const float* __restrict__ Wih1, const float* __restrict__ Whh1,
    const float* __restrict__ bih1, const float* __restrict__ bhh1,
    const float* __restrict__ LW, const float* __restrict__ Lb,
    float* __restrict__ raw, float* __restrict__ part)
{
    __shared__ float sWih0[80], sB0[80], sB1[80];
    __shared__ float sWhh0[1600], sWih1[1600], sWhh1[1600];
    __shared__ float sLW[HID];
    int tid = threadIdx.x;
    for (int k = tid; k < 80; k += 256) {
        sWih0[k] = Wih0[k];
        sB0[k] = bih0[k] + bhh0[k];
        sB1[k] = bih1[k] + bhh1[k];
    }
    for (int k = tid; k < 1600; k += 256) {
        sWhh0[k] = Whh0[k]; sWih1[k] = Wih1[k]; sWhh1[k] = Whh1[k];
    }
    if (tid < HID) sLW[tid] = LW[tid];
    __syncthreads();

    int n = blockIdx.x * 256 + tid;
    float d = diag[n];
    float x = logf(fabsf(d)) * 0.1f;
    x = fminf(fmaxf(x, -1.f), 1.f);

    float hp[HID], h1[HID];
    const float* h0p = h0 + (size_t)n * HID;
    const float* c0p = c0 + (size_t)n * HID;
#pragma unroll
    for (int j = 0; j < HID; j++) hp[j] = h0p[j];
    for (int jh = 0; jh < HID; jh++) {
        float gi = sB0[jh]      + sWih0[jh] * x;
        float gf = sB0[20 + jh] + sWih0[20 + jh] * x;
        float gg = sB0[40 + jh] + sWih0[40 + jh] * x;
        float go = sB0[60 + jh] + sWih0[60 + jh] * x;
#pragma unroll
        for (int j = 0; j < HID; j++) {
            float hv = hp[j];
            gi = fmaf(sWhh0[jh * 20 + j], hv, gi);
            gf = fmaf(sWhh0[(20 + jh) * 20 + j], hv, gf);
            gg = fmaf(sWhh0[(40 + jh) * 20 + j], hv, gg);
            go = fmaf(sWhh0[(60 + jh) * 20 + j], hv, go);
        }
        float cc = sigm(gf) * c0p[jh] + sigm(gi) * tanhf(gg);
        h1[jh] = sigm(go) * tanhf(cc);
    }
    const float* h1p = h0 + (size_t)N * HID + (size_t)n * HID;
    const float* c1p = c0 + (size_t)N * HID + (size_t)n * HID;
    float hb[HID];
#pragma unroll
    for (int j = 0; j < HID; j++) hb[j] = h1p[j];
    float o = 0.f;
    for (int jh = 0; jh < HID; jh++) {
        float gi = sB1[jh], gf = sB1[20 + jh], gg = sB1[40 + jh], go = sB1[60 + jh];
#pragma unroll
        for (int j = 0; j < HID; j++) {
            float a = h1[j], b = hb[j];
            gi = fmaf(sWih1[jh * 20 + j], a, fmaf(sWhh1[jh * 20 + j], b, gi));
            gf = fmaf(sWih1[(20 + jh) * 20 + j], a, fmaf(sWhh1[(20 + jh) * 20 + j], b, gf));
            gg = fmaf(sWih1[(40 + jh) * 20 + j], a, fmaf(sWhh1[(40 + jh) * 20 + j], b, gg));
            go = fmaf(sWih1[(60 + jh) * 20 + j], a, fmaf(sWhh1[(60 + jh) * 20 + j], b, go));
        }
        float cc = sigm(gf) * c1p[jh] + sigm(gi) * tanhf(gg);
        float h2 = sigm(go) * tanhf(cc);
        o = fmaf(sLW[jh], h2, o);
    }
    float val = (o + Lb[0]) * 0.1f;
    raw[n] = val;

    __shared__ float red[256];
    red[tid] = val; __syncthreads();
    for (int s = 128; s > 0; s >>= 1) { if (tid < s) red[tid] += red[tid + s]; __syncthreads(); }
    if (tid == 0) part[blockIdx.x] = red[0];
}

__global__ void meansK() {
    if (threadIdx.x == 0) {
        float s = 0.f; for (int i = 0; i < 32; i++) s += g_partL[i];
        g_means[0] = s / (float)RDIM;
        float t = 0.f; for (int i = 0; i < 8; i++) t += g_partR[i];
        g_means[1] = t / (float)CDIM;
    }
}

__global__ void applyK(const float* __restrict__ raw, const float* __restrict__ before,
                       int mi, float* __restrict__ outv) {
    int i = blockIdx.x * 256 + threadIdx.x;
    outv[i] = fmaxf(raw[i] - g_means[mi] + 1.0f, before[i]);
}

__global__ void p0K() {
    size_t idx = (size_t)blockIdx.x * 256 + threadIdx.x;
    int i = (int)(idx & (RDIM - 1));
    int q = (int)(idx >> 13);
    g_P0[idx] = g_Lv[i] * g_G[idx] * g_Rv[q];
}

// ---------------- Cholesky ----------------
__global__ void cholDiagK(int k0) {
    __shared__ float S[64][65];
    int t = threadIdx.x;
    for (int e = t; e < 4096; e += 64) {
        int a = e & 63, b = e >> 6;
        S[a][b] = g_Gram[(size_t)(k0 + b) * CDIM + (k0 + a)];
    }
    __syncthreads();
    for (int j = 0; j < 64; j++) {
        if (t == 0) S[j][j] = sqrtf(S[j][j]);
        __syncthreads();
        float rjj = S[j][j];
        if (t > j) S[j][t] /= rjj;
        __syncthreads();
        if (t > j) {
            float sjt = S[j][t];
            for (int a = j + 1; a <= t; a++) S[a][t] -= S[j][a] * sjt;
        }
        __syncthreads();
    }
    for (int e = t; e < 4096; e += 64) {
        int a = e & 63, b = e >> 6;
        if (a <= b) g_Gram[(size_t)(k0 + b) * CDIM + (k0 + a)] = S[a][b];
    }
}

__global__ void cholTrsmK(int k0) {
    __shared__ float Rkk[64][65];
    __shared__ float Xs[64][65];
    int t = threadIdx.x;
    int qb = k0 + 64 + blockIdx.x * 64;
    for (int e = t; e < 4096; e += 64) {
        int a = e & 63, b = e >> 6;
        Rkk[a][b] = g_Gram[(size_t)(k0 + b) * CDIM + (k0 + a)];
        Xs[a][b]  = g_Gram[(size_t)(qb + b) * CDIM + (k0 + a)];
    }
    __syncthreads();
    for (int a = 0; a < 64; a++) {
        float sum = 0.f;
        for (int b = 0; b < a; b++) sum = fmaf(Rkk[b][a], Xs[b][t], sum);
        Xs[a][t] = (Xs[a][t] - sum) / Rkk[a][a];
    }
    __syncthreads();
    for (int e = t; e < 4096; e += 64) {
        int a = e & 63, b = e >> 6;
        g_Gram[(size_t)(qb + b) * CDIM + (k0 + a)] = Xs[a][b];
    }
}

__global__ void invDiagK() {
    int k0 = blockIdx.x * 64;
    __shared__ float U[64][65];
    __shared__ float Xs[64][65];
    int t = threadIdx.x;
    for (int e = t; e < 4096; e += 64) {
        int a = e & 63, b = e >> 6;
        U[a][b] = (a <= b) ? g_Gram[(size_t)(k0 + b) * CDIM + (k0 + a)] : 0.f;
        Xs[a][b] = 0.f;
    }
    __syncthreads();
    for (int a = 63; a >= 0; a--) {
        if (a <= t) {
            float sum = (a == t) ? 1.f : 0.f;
            for (int b = a + 1; b <= t; b++) sum = fmaf(-U[a][b], Xs[b][t], sum);
            Xs[a][t] = sum / U[a][a];
        }
    }
    __syncthreads();
    for (int e = t; e < 4096; e += 64) {
        int a = e & 63, b = e >> 6;
        g_Rinv[(size_t)(k0 + b) * CDIM + (k0 + a)] = Xs[a][b];
    }
}

extern "C" void kernel_launch(void* const* d_in, const int* in_sizes, int n_in,
                              void* d_out, int out_size) {
    const float* s   = (const float*)d_in[0];
    const float* sg  = (const float*)d_in[1];
    const float* Lh0 = (const float*)d_in[2];
    const float* Lc0 = (const float*)d_in[3];
    const float* Rh0 = (const float*)d_in[4];
    const float* Rc0 = (const float*)d_in[5];
    const float* Lbef = (const float*)d_in[6];
    const float* Rbef = (const float*)d_in[7];
    const float* Wih0 = (const float*)d_in[8];
    const float* Whh0 = (const float*)d_in[9];
    const float* bih0 = (const float*)d_in[10];
    const float* bhh0 = (const float*)d_in[11];
    const float* Wih1 = (const float*)d_in[12];
    const float* Whh1 = (const float*)d_in[13];
    const float* bih1 = (const float*)d_in[14];
    const float* bhh1 = (const float*)d_in[15];
    const float* LW = (const float*)d_in[16];
    const float* Lb = (const float*)d_in[17];
    const float* RW = (const float*)d_in[18];
    const float* Rb = (const float*)d_in[19];
    float* out = (float*)d_out;

    float *gG, *gP0, *gB, *gA, *gAs, *gGram, *gRinv, *gT;
    float *gdL, *gdR, *glraw, *grraw, *gpartL, *gpartR, *gLv, *gRv;
    cudaGetSymbolAddress((void**)&gG, g_G);
    cudaGetSymbolAddress((void**)&gP0, g_P0);
    cudaGetSymbolAddress((void**)&gB, g_B);
    cudaGetSymbolAddress((void**)&gA, g_A);
    cudaGetSymbolAddress((void**)&gAs, g_As);
    cudaGetSymbolAddress((void**)&gGram, g_Gram);
    cudaGetSymbolAddress((void**)&gRinv, g_Rinv);
    cudaGetSymbolAddress((void**)&gT, g_T);
    cudaGetSymbolAddress((void**)&gdL, g_dL);
    cudaGetSymbolAddress((void**)&gdR, g_dR);
    cudaGetSymbolAddress((void**)&glraw, g_lraw);
    cudaGetSymbolAddress((void**)&grraw, g_rraw);
    cudaGetSymbolAddress((void**)&gpartL, g_partL);
    cudaGetSymbolAddress((void**)&gpartR, g_partR);
    cudaGetSymbolAddress((void**)&gLv, g_Lv);
    cudaGetSymbolAddress((void**)&gRv, g_Rv);

    // A = M^T * (0.1*Mgrad)
    tgemm_tn<<<dim3(16, 16), 256>>>(s, RDIM, sg, RDIM, nullptr, gA, CDIM, RDIM, 0.1f, 0);
    symK<<<CDIM * CDIM / 256, 256>>>(gA, gAs);
    // G = 0.1*Mgrad - M*As
    tgemm_nn<<<dim3(64, 16), 256>>>(s, RDIM, gAs, CDIM, sg, 0.1f, nullptr, 0.f, -1.f, gG, RDIM, CDIM, 0);
    // Gram diagonals
    rowsqK<<<dim3(32, 16), 256>>>();
    rowcombK<<<32, 256>>>();
    colsqK<<<CDIM, 256>>>();
    // LSTMs
    lstmK<<<32, 256>>>(RDIM, gdL, Lh0, Lc0, Wih0, Whh0, bih0, bhh0, Wih1, Whh1, bih1, bhh1, LW, Lb, glraw, gpartL);
    lstmK<<<8, 256>>>(CDIM, gdR, Rh0, Rc0, Wih0, Whh0, bih0, bhh0, Wih1, Whh1, bih1, bhh1, RW, Rb, grraw, gpartR);
    meansK<<<1, 32>>>();
    applyK<<<32, 256>>>(glraw, Lbef, 0, gLv);
    applyK<<<8, 256>>>(grraw, Rbef, 1, gRv);
    // P0 = Lv . G . Rv
    p0K<<<(unsigned)((size_t)RDIM * CDIM / 256), 256>>>();
    // A2 = M^T*P0 ; As2 = sym ; B = M*As2 + s - P0
    tgemm_tn<<<dim3(16, 16), 256>>>(s, RDIM, gP0, RDIM, nullptr, gA, CDIM, RDIM, 1.f, 0);
    symK<<<CDIM * CDIM / 256, 256>>>(gA, gAs);
    tgemm_nn<<<dim3(64, 16), 256>>>(s, RDIM, gAs, CDIM, s, 1.f, gP0, -1.f, 1.f, gB, RDIM, CDIM, 0);
    // Gram = B^T B (upper)
    tgemm_tn<<<dim3(16, 16), 256>>>(gB, RDIM, gB, RDIM, nullptr, gGram, CDIM, RDIM, 1.f, 1);
    // blocked Cholesky
    for (int k = 0; k < NBLK; k++) {
        cholDiagK<<<1, 64>>>(k * 64);
        int nb = NBLK - 1 - k;
        if (nb > 0) {
            cholTrsmK<<<nb, 64>>>(k * 64);
            int r0 = (k + 1) * 64;
            const float* panel = gGram + (size_t)r0 * CDIM + k * 64;
            float* base = gGram + (size_t)r0 * CDIM + r0;
            gemm_tn<<<dim3(nb, nb), 256>>>(panel, CDIM, panel, CDIM, base, base, CDIM, 64, -1.f, 1);
        }
    }
    // Rinv via recursive doubling
    zeroBufK<<<CDIM * CDIM / 256, 256>>>(gRinv);
    invDiagK<<<NBLK, 64>>>();
    for (int b = 64; b <= 1024; b *= 2) {
        int npairs = CDIM / (2 * b);
        dim3 g1(b / 64, b / 64, npairs);
        long long strideP = (long long)2 * b * (CDIM + 1);
        // T = A12 * X22
        gemm_nn_b<<<g1, 256>>>(gGram + (size_t)b * CDIM, strideP, CDIM,
                               gRinv + (size_t)b * CDIM + b, strideP, CDIM,
                               gT, (long long)b * b, b, b, 1.f);
        // X12 = -X11 * T
        gemm_nn_b<<<g1, 256>>>(gRinv, strideP, CDIM,
                               gT, (long long)b * b, b,
                               gRinv + (size_t)b * CDIM, strideP, CDIM, b, -1.f);
    }
    // Q = B * Rinv -> out
    tgemm_nn<<<dim3(64, 16), 256>>>(gB, RDIM, gRinv, CDIM, nullptr, 0.f, nullptr, 0.f, 1.f, out, RDIM, CDIM, 1);
}